// round 2
// baseline (speedup 1.0000x reference)
#include <cuda_runtime.h>

#define M_MOL 64
#define NA    24
#define P     276
#define T_ROWS 6000
#define TT    48
#define NBLK  (T_ROWS/TT)      // 125
#define NTHR  384
#define QC    0.22360679774997896f   // sqrt(5)/sig, sig=10
#define C0    0.0166666666666667f    // 5/(3*sig^2) = 1/60
#define PPAD  288                    // P padded to 24*12
#define NQ    4                      // reduction quadrants

// ---------------- scratch ----------------
__device__ float g_qxsT[P * M_MOL];     // [p][m]  q * xs
__device__ float g_xs3 [M_MOL * P];     // [m][p]  xs^3
__device__ float g_nrm [M_MOL];         // |q xs_m|^2
__device__ float g_Apart [NBLK * M_MOL * P];
__device__ float g_A2    [NQ * M_MOL * P];
__device__ float g_S1part[NBLK * M_MOL];
__device__ float g_Espart[NBLK * M_MOL];

// ---------------- f32x2 helpers ----------------
__device__ __forceinline__ unsigned long long pk2(float lo, float hi) {
    unsigned long long r;
    asm("mov.b64 %0, {%1,%2};" : "=l"(r) : "f"(lo), "f"(hi));
    return r;
}
__device__ __forceinline__ unsigned long long fma2(unsigned long long a,
                                                   unsigned long long b,
                                                   unsigned long long c) {
    unsigned long long d;
    asm("fma.rn.f32x2 %0, %1, %2, %3;" : "=l"(d) : "l"(a), "l"(b), "l"(c));
    return d;
}
__device__ __forceinline__ void upk2(unsigned long long v, float& lo, float& hi) {
    asm("mov.b64 {%0,%1}, %2;" : "=f"(lo), "=f"(hi) : "l"(v));
}

// ---------------- kernel 1: per-molecule descriptors ----------------
__global__ void k_prep_m(const float* __restrict__ Rs) {
    int m = blockIdx.x;
    int p = threadIdx.x;
    __shared__ float s_nrm;
    if (p == 0) s_nrm = 0.0f;
    __syncthreads();
    if (p < P) {
        int i = 1;
        while (i * (i + 1) / 2 <= p) i++;
        int j = p - i * (i - 1) / 2;
        const float* a = Rs + (m * NA + i) * 3;
        const float* b = Rs + (m * NA + j) * 3;
        float dx = a[0] - b[0], dy = a[1] - b[1], dz = a[2] - b[2];
        float r2 = dx * dx + dy * dy + dz * dz;
        float xs = rsqrtf(r2);
        float qxs = QC * xs;
        g_qxsT[p * M_MOL + m] = qxs;
        g_xs3[m * P + p] = xs * xs * xs;
        atomicAdd(&s_nrm, qxs * qxs);
    }
    __syncthreads();
    if (p == 0) g_nrm[m] = s_nrm;
}

// ---------------- kernel 2: main fused dual-GEMM (f32x2) ----------------
// smem (floats):
//  sX   [48][288]  @ 0       (13824)   q * xs_train, t-major, p padded w/ 0
//  sJ   [48][288]  @ 13824   (13824)
//  sQx  [P][64]    @ 27648   (17664)
//  sW1d [48][128]  @ 45312   (6144)    w1 duplicated pairs
//  sW2d [48][128]  @ 51456   (6144)
//  sTn  [48]       @ 57600
//  sTc  [48]       @ 57648
//  sNrm [64]       @ 57696
//  sS1  [64]       @ 57760
//  sEs  [64]       @ 57824   -> 57888 floats = 231552 B
#define SMEM_FLOATS 57888
#define SMEM_BYTES  (SMEM_FLOATS * 4)

__global__ __launch_bounds__(NTHR, 1)
void k_main(const float* __restrict__ xst, const float* __restrict__ Jx) {
    extern __shared__ float sm[];
    float* sX   = sm;
    float* sJ   = sm + 13824;
    float* sQx  = sm + 27648;
    float* sW1d = sm + 45312;
    float* sW2d = sm + 51456;
    float* sTn  = sm + 57600;
    float* sTc  = sm + 57648;
    float* sNrm = sm + 57696;
    float* sS1  = sm + 57760;
    float* sEs  = sm + 57824;

    const int tid  = threadIdx.x;
    const int wid  = tid >> 5;
    const int lane = tid & 31;
    const int blk  = blockIdx.x;
    const int t0   = blk * TT;

    // ---- stage train tiles (t-major, scaled, zero-padded) ----
    for (int t = wid; t < TT; t += 12) {
        const float4* src = (const float4*)(xst + (size_t)(t0 + t) * P);
        const float4* srj = (const float4*)(Jx  + (size_t)(t0 + t) * P);
        float4* dx = (float4*)(sX + t * PPAD);
        float4* dj = (float4*)(sJ + t * PPAD);
        for (int c = lane; c < 72; c += 32) {
            float4 v, w;
            if (c < 69) { v = src[c]; w = srj[c]; }
            else        { v = make_float4(0.f,0.f,0.f,0.f); w = v; }
            v.x *= QC; v.y *= QC; v.z *= QC; v.w *= QC;
            dx[c] = v; dj[c] = w;
        }
    }
    // ---- stage qxs^T ----
    {
        const float4* src4 = (const float4*)g_qxsT;
        float4* dst4 = (float4*)sQx;
        #pragma unroll 4
        for (int i = tid; i < P * M_MOL / 4; i += NTHR) dst4[i] = src4[i];
    }
    if (tid < M_MOL) {
        sNrm[tid] = g_nrm[tid];
        sS1[tid] = 0.0f;
        sEs[tid] = 0.0f;
    }
    __syncthreads();

    // ---- per-t norms/dots from smem (fused former k_prep_t) ----
    {
        #pragma unroll
        for (int k = 0; k < 4; k++) {
            int t = wid * 4 + k;
            const float* xr = sX + t * PPAD;
            const float* jr = sJ + t * PPAD;
            float tn = 0.0f, tc = 0.0f;
            #pragma unroll
            for (int c = lane; c < PPAD; c += 32) {
                float x = xr[c];
                tn = fmaf(x, x, tn);
                tc = fmaf(x, jr[c], tc);
            }
            #pragma unroll
            for (int o = 16; o; o >>= 1) {
                tn += __shfl_down_sync(0xffffffffu, tn, o);
                tc += __shfl_down_sync(0xffffffffu, tc, o);
            }
            if (lane == 0) { sTn[t] = tn; sTc[t] = tc; }
        }
    }
    __syncthreads();

    // ---- phase A: G1 = qxs.qxst^T, G2 = qxs.Jx^T  (f32x2 over m-pairs) ----
    const int ty = tid & 15;
    const int tx = tid >> 4;       // 0..23
    const int m4 = ty * 4;
    const int t2 = tx * 2;

    unsigned long long g1[2][2] = {{0ull,0ull},{0ull,0ull}};
    unsigned long long g2[2][2] = {{0ull,0ull},{0ull,0ull}};
    {
        const float* xr0 = sX + t2 * PPAD;
        const float* xr1 = xr0 + PPAD;
        const float* jr0 = sJ + t2 * PPAD;
        const float* jr1 = jr0 + PPAD;
        #pragma unroll 4
        for (int p = 0; p < P; p++) {
            ulonglong2 a = *(const ulonglong2*)(sQx + p * M_MOL + m4);
            unsigned long long X0 = pk2(xr0[p], xr0[p]);
            unsigned long long X1 = pk2(xr1[p], xr1[p]);
            unsigned long long J0 = pk2(jr0[p], jr0[p]);
            unsigned long long J1 = pk2(jr1[p], jr1[p]);
            g1[0][0] = fma2(a.x, X0, g1[0][0]);
            g1[1][0] = fma2(a.y, X0, g1[1][0]);
            g1[0][1] = fma2(a.x, X1, g1[0][1]);
            g1[1][1] = fma2(a.y, X1, g1[1][1]);
            g2[0][0] = fma2(a.x, J0, g2[0][0]);
            g2[1][0] = fma2(a.y, J0, g2[1][0]);
            g2[0][1] = fma2(a.x, J1, g2[0][1]);
            g2[1][1] = fma2(a.y, J1, g2[1][1]);
        }
    }

    // ---- weights ----
    #pragma unroll
    for (int mp = 0; mp < 2; mp++) {
        #pragma unroll
        for (int j = 0; j < 2; j++) {
            int t = t2 + j;
            float tn = sTn[t], tc = sTc[t];
            float G1lo, G1hi, G2lo, G2hi;
            upk2(g1[mp][j], G1lo, G1hi);
            upk2(g2[mp][j], G2lo, G2hi);
            #pragma unroll
            for (int h = 0; h < 2; h++) {
                int m = m4 + 2 * mp + h;
                float G1 = h ? G1hi : G1lo;
                float G2 = h ? G2hi : G2lo;
                float d2   = fmaf(-2.0f, G1, sNrm[m] + tn);
                float dist = sqrtf(fmaxf(d2, 0.0f));
                float e    = C0 * __expf(-dist);
                float dot  = G2 - tc;
                float w1   = e * dot;
                float w2   = fmaf(e, dist, e);
                *(unsigned long long*)&sW1d[t * 128 + 2 * m] = pk2(w1, w1);
                *(unsigned long long*)&sW2d[t * 128 + 2 * m] = pk2(w2, w2);
                atomicAdd(&sS1[m], w1);
                atomicAdd(&sEs[m], w2 * dot);
            }
        }
    }
    __syncthreads();

    // ---- per-m scalars out ----
    if (tid < M_MOL) {
        g_S1part[blk * M_MOL + tid] = sS1[tid];
        g_Espart[blk * M_MOL + tid] = sEs[tid];
    }

    // ---- phase B: A[m,p] = sum_t (w1*qxst + w2*Jx)  (f32x2 over p-pairs) ----
    const int pg = tid >> 4;        // 0..23 (pg 23 is pure padding)
    const int p0 = pg * 12;
    unsigned long long acc[4][6];
    #pragma unroll
    for (int mi = 0; mi < 4; mi++)
        #pragma unroll
        for (int pp = 0; pp < 6; pp++) acc[mi][pp] = 0ull;

    #pragma unroll 2
    for (int t = 0; t < TT; t++) {
        const float* xb = sX + t * PPAD + p0;
        const float* jb = sJ + t * PPAD + p0;
        ulonglong2 xA = *(const ulonglong2*)(xb);
        ulonglong2 xB = *(const ulonglong2*)(xb + 4);
        ulonglong2 xC = *(const ulonglong2*)(xb + 8);
        ulonglong2 jA = *(const ulonglong2*)(jb);
        ulonglong2 jB = *(const ulonglong2*)(jb + 4);
        ulonglong2 jC = *(const ulonglong2*)(jb + 8);
        unsigned long long xp[6] = {xA.x, xA.y, xB.x, xB.y, xC.x, xC.y};
        unsigned long long jp[6] = {jA.x, jA.y, jB.x, jB.y, jC.x, jC.y};
        unsigned long long w1d[4], w2d[4];
        #pragma unroll
        for (int mi = 0; mi < 4; mi++) {
            w1d[mi] = *(const unsigned long long*)&sW1d[t * 128 + 2 * (m4 + mi)];
            w2d[mi] = *(const unsigned long long*)&sW2d[t * 128 + 2 * (m4 + mi)];
        }
        #pragma unroll
        for (int mi = 0; mi < 4; mi++)
            #pragma unroll
            for (int pp = 0; pp < 6; pp++)
                acc[mi][pp] = fma2(w1d[mi], xp[pp], fma2(w2d[mi], jp[pp], acc[mi][pp]));
    }
    __syncthreads();

    // ---- unpack acc -> smem -> coalesced global write ----
    float* sAcc = sm;   // reuse sX region (17664 < 27648 floats)
    if (pg < 23) {
        #pragma unroll
        for (int mi = 0; mi < 4; mi++) {
            #pragma unroll
            for (int pp = 0; pp < 6; pp++) {
                float lo, hi;
                upk2(acc[mi][pp], lo, hi);
                sAcc[(m4 + mi) * P + p0 + 2 * pp]     = lo;
                sAcc[(m4 + mi) * P + p0 + 2 * pp + 1] = hi;
            }
        }
    }
    __syncthreads();
    float* gA = g_Apart + (size_t)blk * M_MOL * P;
    #pragma unroll 4
    for (int idx = tid; idx < M_MOL * P; idx += NTHR) gA[idx] = sAcc[idx];
}

// ---------------- kernel 3: first-stage partial reduction ----------------
__global__ void k_reduce() {
    int m = blockIdx.x >> 2;
    int q = blockIdx.x & 3;
    int p = threadIdx.x;
    if (p >= P) return;
    int b0 = q * 32;
    int b1 = (b0 + 32 < NBLK) ? b0 + 32 : NBLK;
    float s = 0.0f;
    for (int b = b0; b < b1; b++)
        s += g_Apart[((size_t)b * M_MOL + m) * P + p];
    g_A2[((size_t)q * M_MOL + m) * P + p] = s;
}

// ---------------- kernel 4: finalize Fs and Es ----------------
__global__ void k_final(const float* __restrict__ Rs, float* __restrict__ out) {
    int m = blockIdx.x;
    int tid = threadIdx.x;            // 288 threads
    __shared__ float sFsx[P];
    __shared__ float sS1, sEs;

    if (tid < 32) {
        float s1 = 0.0f, es = 0.0f;
        for (int b = tid; b < NBLK; b += 32) {
            s1 += g_S1part[b * M_MOL + m];
            es += g_Espart[b * M_MOL + m];
        }
        #pragma unroll
        for (int o = 16; o; o >>= 1) {
            s1 += __shfl_down_sync(0xffffffffu, s1, o);
            es += __shfl_down_sync(0xffffffffu, es, o);
        }
        if (tid == 0) { sS1 = s1; sEs = es; }
    }
    __syncthreads();

    if (tid < P) {
        float a = 0.0f;
        #pragma unroll
        for (int q = 0; q < NQ; q++)
            a += g_A2[((size_t)q * M_MOL + m) * P + tid];
        sFsx[tid] = (g_qxsT[tid * M_MOL + m] * sS1 - a) * g_xs3[m * P + tid];
    }
    __syncthreads();

    if (tid < NA * 3) {
        int atom = tid / 3, d = tid % 3;
        float ra = Rs[(m * NA + atom) * 3 + d];
        float f = 0.0f;
        #pragma unroll
        for (int b = 0; b < NA; b++) {
            if (b == atom) continue;
            int hi = (atom > b) ? atom : b;
            int lo = (atom > b) ? b : atom;
            int pi = hi * (hi - 1) / 2 + lo;
            f = fmaf(Rs[(m * NA + b) * 3 + d] - ra, sFsx[pi], f);
        }
        out[M_MOL + (m * NA + atom) * 3 + d] = f;
    }
    if (tid == 0) out[m] = sEs * (1.0f / QC);
}

// ---------------- entry ----------------
extern "C" void kernel_launch(void* const* d_in, const int* in_sizes, int n_in,
                              void* d_out, int out_size) {
    const float* Rs  = (const float*)d_in[0];
    const float* xst = (const float*)d_in[1];
    const float* Jx  = (const float*)d_in[2];
    float* out = (float*)d_out;

    cudaFuncSetAttribute(k_main, cudaFuncAttributeMaxDynamicSharedMemorySize, SMEM_BYTES);

    k_prep_m<<<M_MOL, 288>>>(Rs);
    k_main<<<NBLK, NTHR, SMEM_BYTES>>>(xst, Jx);
    k_reduce<<<M_MOL * NQ, 288>>>();
    k_final<<<M_MOL, 288>>>(Rs, out);
}